// round 13
// baseline (speedup 1.0000x reference)
#include <cuda_runtime.h>

#define DD   256
#define NN   8192
#define EE   8191
#define ALPHA 0.2f
#define GRID 128

// ---------------- scratch (allocation-free __device__ globals, zero-init) -------
__device__ __align__(16) float g_H[NN * DD];   // H = X @ W^T (tf32-rounded inputs)
__device__ __align__(16) float g_w12[2 * DD];
__device__ float g_p[NN];
__device__ float g_q[NN];
__device__ float g_cA[NN];
__device__ float g_cB[NN];
__device__ int   g_sA[NN];
__device__ int   g_sB[NN];
__device__ unsigned g_b1, g_b2, g_b3, g_br;    // self-resetting each call

__device__ __forceinline__ unsigned f2tf(float f) {
    unsigned r; asm("cvt.rna.tf32.f32 %0, %1;" : "=r"(r) : "f"(f)); return r;
}
__device__ __forceinline__ float tfbits(float f) { return __uint_as_float(f2tf(f)); }
__device__ __forceinline__ float lrelu(float v) { return v > 0.f ? v : ALPHA * v; }
__device__ __forceinline__ unsigned su32(const void* p) {
    return (unsigned)__cvta_generic_to_shared(p);
}
__device__ __forceinline__ float dot4(float4 a, float4 b) {
    return a.x * b.x + a.y * b.y + a.z * b.z + a.w * b.w;
}
__device__ __forceinline__ void gridbar(unsigned* ctr) {
    __syncthreads();
    if (threadIdx.x == 0) {
        __threadfence();
        atomicAdd(ctr, 1u);
        while (*(volatile unsigned*)ctr < GRID) __nanosleep(32);
        __threadfence();
    }
    __syncthreads();
}

// smem: A panel 8 chunks x [128][36]; B tile 8 chunks x [64][36]
#define CH    (128 * 36)
#define BCH   (64 * 36)
#define APANF (8 * CH)                 // 36864 floats
#define BPANF (8 * BCH)                // 18432 floats
#define SMEMB ((APANF + BPANF) * 4)    // 221,184 B

__global__ __launch_bounds__(512, 1) void k_fused(
    const float* __restrict__ x, const float* __restrict__ W,
    const float* __restrict__ a,
    const int* __restrict__ dep, const int* __restrict__ gov,
    float* __restrict__ out)
{
    extern __shared__ float sm[];
    float* Asm = sm;
    float* Bsm = sm + APANF;
    int tid = threadIdx.x;
    int blk = blockIdx.x;
    int wid = tid >> 5, lane = tid & 31;

    int m0  = (blk >> 1) * 128;
    int nb0 = (blk & 1) * 128;

    // ======== phase 0: w12, 2 columns per block (perfectly balanced) ===========
    {
        float* s1 = sm;            // [2][256]
        float* s2 = sm + 512;
        int j = tid >> 1, c = tid & 1;
        float v = W[j * DD + blk * 2 + c];
        s1[c * 256 + j] = a[j] * v;
        s2[c * 256 + j] = a[DD + j] * v;
        __syncthreads();
        int seg = tid >> 8, idx = tid & 255;
#pragma unroll
        for (int off = 128; off >= 1; off >>= 1) {
            if (idx < off) {
                s1[seg * 256 + idx] += s1[seg * 256 + idx + off];
                s2[seg * 256 + idx] += s2[seg * 256 + idx + off];
            }
            __syncthreads();
        }
        if (idx == 0) {
            g_w12[blk * 2 + seg]      = s1[seg * 256];
            g_w12[DD + blk * 2 + seg] = s2[seg * 256];
        }
        __syncthreads();
    }

    // ======== phase 1: H = X @ W^T, K-resident panels, barrier-free MMA ========
    {
        // fill A panel: X rows m0..m0+127, all K=256, tf32-rounded
        {
            int row = tid >> 2, q = tid & 3;
            const float4* x4 = (const float4*)x;
            int gb = (m0 + row) * 64 + q * 2;
            int st = row * 36 + q * 8;
#pragma unroll
            for (int c = 0; c < 8; c++) {
                float4 v0 = x4[gb + c * 8], v1 = x4[gb + c * 8 + 1];
                float* d = Asm + c * CH + st;
                d[0] = tfbits(v0.x); d[1] = tfbits(v0.y);
                d[2] = tfbits(v0.z); d[3] = tfbits(v0.w);
                d[4] = tfbits(v1.x); d[5] = tfbits(v1.y);
                d[6] = tfbits(v1.z); d[7] = tfbits(v1.w);
            }
        }

        // fragment addressing: 16 warps 4(m) x 4(n), warp tile 32x16
        int wm = (wid & 3) * 32;
        int wn = (wid >> 2) * 16;
        int aRow = wm + (lane & 7) + ((lane & 8) ? 8 : 0);
        int aColF = (lane & 16) ? 4 : 0;
        unsigned aB = su32(Asm + aRow * 36 + aColF);
        int bRow = wn + (lane & 7);
        int bColF = (lane & 8) ? 4 : 0;
        unsigned bB = su32(Bsm + bRow * 36 + bColF);

#pragma unroll 1
        for (int t = 0; t < 2; t++) {
            int nb = nb0 + t * 64;
            __syncthreads();               // A/B panel safe to (re)fill
            {
                int row = tid >> 3, f = tid & 7;
                const float4* W4 = (const float4*)W;
                int gb = (nb + row) * 64 + f;
                int st = row * 36 + f * 4;
#pragma unroll
                for (int c = 0; c < 8; c++) {
                    float4 v = W4[gb + c * 8];
                    float* d = Bsm + c * BCH + st;
                    d[0] = tfbits(v.x); d[1] = tfbits(v.y);
                    d[2] = tfbits(v.z); d[3] = tfbits(v.w);
                }
            }
            __syncthreads();

            float acc[2][2][4];
#pragma unroll
            for (int i = 0; i < 2; i++)
#pragma unroll
                for (int j = 0; j < 2; j++)
#pragma unroll
                    for (int v = 0; v < 4; v++) acc[i][j][v] = 0.f;

#pragma unroll
            for (int kt = 0; kt < 8; kt++) {
                unsigned aS = aB + kt * CH * 4;
                unsigned bS = bB + kt * BCH * 4;
#pragma unroll
                for (int ks = 0; ks < 4; ks++) {
                    int k = ks * 8;
                    unsigned af[2][4], bf[2][2];
#pragma unroll
                    for (int mf = 0; mf < 2; mf++)
                        asm volatile("ldmatrix.sync.aligned.m8n8.x4.shared.b16 {%0,%1,%2,%3}, [%4];"
                            : "=r"(af[mf][0]), "=r"(af[mf][1]), "=r"(af[mf][2]), "=r"(af[mf][3])
                            : "r"(aS + (unsigned)((mf * 576 + k) * 4)));
#pragma unroll
                    for (int nf = 0; nf < 2; nf++)
                        asm volatile("ldmatrix.sync.aligned.m8n8.x2.shared.b16 {%0,%1}, [%2];"
                            : "=r"(bf[nf][0]), "=r"(bf[nf][1])
                            : "r"(bS + (unsigned)((nf * 288 + k) * 4)));
#pragma unroll
                    for (int mf = 0; mf < 2; mf++)
#pragma unroll
                        for (int nf = 0; nf < 2; nf++)
                            asm volatile(
                                "mma.sync.aligned.m16n8k8.row.col.f32.tf32.tf32.f32 "
                                "{%0,%1,%2,%3}, {%4,%5,%6,%7}, {%8,%9}, {%0,%1,%2,%3};"
                                : "+f"(acc[mf][nf][0]), "+f"(acc[mf][nf][1]),
                                  "+f"(acc[mf][nf][2]), "+f"(acc[mf][nf][3])
                                : "r"(af[mf][0]), "r"(af[mf][1]), "r"(af[mf][2]), "r"(af[mf][3]),
                                  "r"(bf[nf][0]), "r"(bf[nf][1]));
                }
            }

            // write H tile (raw fp32, lrelu deferred to gather phase)
            int er = m0 + wm + (lane >> 2);
            int ec = nb + wn + (lane & 3) * 2;
#pragma unroll
            for (int mf = 0; mf < 2; mf++) {
#pragma unroll
                for (int nf = 0; nf < 2; nf++) {
                    *(float2*)&g_H[(er + mf * 16) * DD + ec + nf * 8] =
                        make_float2(acc[mf][nf][0], acc[mf][nf][1]);
                    *(float2*)&g_H[(er + mf * 16 + 8) * DD + ec + nf * 8] =
                        make_float2(acc[mf][nf][2], acc[mf][nf][3]);
                }
            }
        }
    }
    gridbar(&g_b1);

    // ======== phase 2: p = x.w1, q = x.w2 (streaming, warp per row) ============
    {
        const float4* x4 = (const float4*)x;
        const float4* w4 = (const float4*)g_w12;
        float4 w1a = w4[lane * 2],      w1b = w4[lane * 2 + 1];
        float4 w2a = w4[64 + lane * 2], w2b = w4[64 + lane * 2 + 1];
        int rb = (blk * 16 + wid) * 4;
#pragma unroll
        for (int i = 0; i < 4; i++) {
            int row = rb + i;
            float4 xa = x4[row * 64 + lane * 2], xb = x4[row * 64 + lane * 2 + 1];
            float p = dot4(xa, w1a) + dot4(xb, w1b);
            float q = dot4(xa, w2a) + dot4(xb, w2b);
#pragma unroll
            for (int o = 16; o; o >>= 1) {
                p += __shfl_xor_sync(0xFFFFFFFFu, p, o);
                q += __shfl_xor_sync(0xFFFFFFFFu, q, o);
            }
            if (lane == 0) { g_p[row] = p; g_q[row] = q; }
        }
    }
    gridbar(&g_b2);

    // ======== phase 3: edge tables (scalar) ====================================
    {
        int e = blk * 512 + tid;
        if (e < EE) {
            int g = gov[e], d = dep[e];
            float s = g_p[g] + g_q[d];
            float coef = (s > 0.f) ? 1.f : (1.f / (float)NN);
            g_cA[d] = 1.f;  g_sA[d] = g;   // h[dep]  = Hx[gov]
            g_cB[g] = coef; g_sB[g] = d;   // h[gov] += coef * Hx[dep]
        }
    }
    gridbar(&g_b3);

    // ======== phase 4: out[r] = lrelu(cA*H[sA] + cB*H[sB]) =====================
    {
        int gt = blk * 512 + tid;
        int row = gt >> 3;
        int c0  = (gt & 7) * 8;           // f4 base within row (64 f4/row)
        float cA = g_cA[row], cB = g_cB[row];
        int   sA = g_sA[row], sB = g_sB[row];
        const float4* H4 = (const float4*)g_H;
        float4* o4 = (float4*)out;
#pragma unroll
        for (int i = 0; i < 8; i++) {
            float4 u = H4[sA * 64 + c0 + i];
            float4 v = H4[sB * 64 + c0 + i];
            float4 o;
            o.x = lrelu(cA * u.x + cB * v.x);
            o.y = lrelu(cA * u.y + cB * v.y);
            o.z = lrelu(cA * u.z + cB * v.z);
            o.w = lrelu(cA * u.w + cB * v.w);
            o4[row * 64 + c0 + i] = o;
        }
    }

    // ---- reset barrier counters for next graph replay (last block does it) ----
    __syncthreads();
    if (tid == 0) {
        unsigned old = atomicAdd(&g_br, 1u);
        if (old == GRID - 1) {
            g_b1 = 0; g_b2 = 0; g_b3 = 0; g_br = 0;
            __threadfence();
        }
    }
}

// ---------------- launch ---------------------------------------------------------
extern "C" void kernel_launch(void* const* d_in, const int* in_sizes, int n_in,
                              void* d_out, int out_size) {
    const float* x   = (const float*)d_in[0];
    const float* W   = (const float*)d_in[1];
    const float* a   = (const float*)d_in[2];
    const int*   dep = (const int*)d_in[3];
    const int*   gov = (const int*)d_in[4];
    float* out = (float*)d_out;

    cudaFuncSetAttribute(k_fused, cudaFuncAttributeMaxDynamicSharedMemorySize, SMEMB);
    k_fused<<<GRID, 512, SMEMB>>>(x, W, a, dep, gov, out);
}

// round 14
// speedup vs baseline: 1.6370x; 1.6370x over previous
#include <cuda_runtime.h>

#define DD   256
#define NN   8192
#define EE   8191
#define ALPHA 0.2f
#define GRID 128

// ---------------- scratch (allocation-free __device__ globals, zero-init) -------
__device__ float g_w12[2 * DD];
// per-output-row gather tables: out_row r = lrelu((cA*x[sA] + cB*x[sB]) @ W^T)
__device__ float g_cA[NN];
__device__ float g_cB[NN];
__device__ int   g_sA[NN];
__device__ int   g_sB[NN];
__device__ unsigned g_bar1, g_bar2, g_bar3;   // self-resetting each call

__device__ __forceinline__ unsigned f2tf(float f) {
    unsigned r; asm("cvt.rna.tf32.f32 %0, %1;" : "=r"(r) : "f"(f)); return r;
}
__device__ __forceinline__ float tfbits(float f) { return __uint_as_float(f2tf(f)); }
__device__ __forceinline__ float lrelu(float v) { return v > 0.f ? v : ALPHA * v; }
__device__ __forceinline__ unsigned su32(const void* p) {
    return (unsigned)__cvta_generic_to_shared(p);
}
__device__ __forceinline__ float dot4(float4 a, float4 b) {
    return a.x * b.x + a.y * b.y + a.z * b.z + a.w * b.w;
}
__device__ __forceinline__ void gridbar(unsigned* ctr) {
    __syncthreads();
    if (threadIdx.x == 0) {
        __threadfence();
        atomicAdd(ctr, 1u);
        while (*(volatile unsigned*)ctr < GRID) __nanosleep(32);
        __threadfence();
    }
    __syncthreads();
}

#define TSTG (128 * 36)

__global__ __launch_bounds__(512, 1) void k_fused(
    const float* __restrict__ x, const float* __restrict__ W,
    const float* __restrict__ a,
    const int* __restrict__ dep, const int* __restrict__ gov,
    float* __restrict__ out)
{
    extern __shared__ float sm[];
    int tid = threadIdx.x;
    int blk = blockIdx.x;

    // ================= phase 0: w12 on blocks 0..15 =================
    if (blk < 16) {
        float* p1 = sm;            // [32][16]
        float* p2 = sm + 512;
        int l = tid & 15, g = tid >> 4;      // col-in-slice, j-group (0..31)
        int col = blk * 16 + l;
        int j0 = g * 8;
        float a1 = 0.f, a2 = 0.f;
#pragma unroll
        for (int i = 0; i < 8; i++) {
            float wv = W[(j0 + i) * DD + col];
            a1 += a[j0 + i] * wv;
            a2 += a[DD + j0 + i] * wv;
        }
        p1[g * 16 + l] = a1; p2[g * 16 + l] = a2;
        __syncthreads();
        if (tid < 32) {
            int half = tid >> 4, c = tid & 15;
            const float* ps = half ? p2 : p1;
            float s = 0.f;
#pragma unroll
            for (int r = 0; r < 32; r++) s += ps[r * 16 + c];
            g_w12[half * DD + blk * 16 + c] = s;
        }
    }
    gridbar(&g_bar1);

    // ================= phase 1: edges (2048 warps x 4, paired gathers) =========
    {
        int wid = tid >> 5, lane = tid & 31;
        int eb = (blk * 16 + wid) * 4;       // 0..8191
        const float4* x4 = (const float4*)x;
        const float4* w4 = (const float4*)g_w12;
        float4 w1a = w4[lane * 2],      w1b = w4[lane * 2 + 1];
        float4 w2a = w4[64 + lane * 2], w2b = w4[64 + lane * 2 + 1];
        int ge[4], de[4];
#pragma unroll
        for (int i = 0; i < 4; i++) {
            int e = eb + i;
            ge[i] = (e < EE) ? gov[e] : 0;
            de[i] = (e < EE) ? dep[e] : 0;
        }
#pragma unroll
        for (int p = 0; p < 2; p++) {        // two edges at a time: MLP 8
            int i0 = p * 2, i1 = p * 2 + 1;
            float4 ag0 = x4[ge[i0] * 64 + lane * 2], ag1 = x4[ge[i0] * 64 + lane * 2 + 1];
            float4 ad0 = x4[de[i0] * 64 + lane * 2], ad1 = x4[de[i0] * 64 + lane * 2 + 1];
            float4 bg0 = x4[ge[i1] * 64 + lane * 2], bg1 = x4[ge[i1] * 64 + lane * 2 + 1];
            float4 bd0 = x4[de[i1] * 64 + lane * 2], bd1 = x4[de[i1] * 64 + lane * 2 + 1];
            float s0 = dot4(ag0, w1a) + dot4(ag1, w1b) + dot4(ad0, w2a) + dot4(ad1, w2b);
            float s1 = dot4(bg0, w1a) + dot4(bg1, w1b) + dot4(bd0, w2a) + dot4(bd1, w2b);
#pragma unroll
            for (int o = 16; o; o >>= 1) {
                s0 += __shfl_xor_sync(0xFFFFFFFFu, s0, o);
                s1 += __shfl_xor_sync(0xFFFFFFFFu, s1, o);
            }
            if (lane == 0 && eb + i0 < EE) {
                float c0 = (s0 > 0.f) ? 1.f : (1.f / (float)NN);
                g_cA[de[i0]] = 1.f; g_sA[de[i0]] = ge[i0];
                g_cB[ge[i0]] = c0;  g_sB[ge[i0]] = de[i0];
            }
            if (lane == 0 && eb + i1 < EE) {
                float c1 = (s1 > 0.f) ? 1.f : (1.f / (float)NN);
                g_cA[de[i1]] = 1.f; g_sA[de[i1]] = ge[i1];
                g_cB[ge[i1]] = c1;  g_sB[ge[i1]] = de[i1];
            }
        }
    }
    gridbar(&g_bar2);

    // ================= phase 2: fused-gather tf32 GEMM (r9 body, x4 B-loads) ===
    {
        float* Asm = sm;              // [2][128*36]
        float* Bsm = sm + 2 * TSTG;   // [2][128*36]
        int m0 = (blk >> 1) * 128;
        int n0 = (blk & 1) * 128;

        int arow = tid >> 2;
        int aq   = tid & 3;
        int row  = m0 + arow;
        float cA = g_cA[row], cB = g_cB[row];
        int   sA = g_sA[row], sB = g_sB[row];

        const float4* x4 = (const float4*)x;
        const float4* W4 = (const float4*)W;
        int aOff = sA * 64 + aq * 2;
        int bOff = sB * 64 + aq * 2;
        int wOff = (n0 + arow) * 64 + aq * 2;
        int st0  = arow * 36 + aq * 8;

        float4 rg[2], rb[2], rw[2];
#pragma unroll
        for (int j = 0; j < 2; j++) { rg[j] = x4[aOff + j]; rb[j] = x4[bOff + j]; rw[j] = W4[wOff + j]; }

#define STORE_TILE(buf) do {                                                  \
        float* Ad = Asm + (buf) * TSTG + st0;                                 \
        float* Bd = Bsm + (buf) * TSTG + st0;                                 \
        _Pragma("unroll")                                                     \
        for (int j = 0; j < 2; j++) {                                         \
            Ad[j*4+0] = tfbits(cA * rg[j].x + cB * rb[j].x);                  \
            Ad[j*4+1] = tfbits(cA * rg[j].y + cB * rb[j].y);                  \
            Ad[j*4+2] = tfbits(cA * rg[j].z + cB * rb[j].z);                  \
            Ad[j*4+3] = tfbits(cA * rg[j].w + cB * rb[j].w);                  \
            Bd[j*4+0] = tfbits(rw[j].x);                                      \
            Bd[j*4+1] = tfbits(rw[j].y);                                      \
            Bd[j*4+2] = tfbits(rw[j].z);                                      \
            Bd[j*4+3] = tfbits(rw[j].w);                                      \
        }                                                                     \
    } while (0)

        STORE_TILE(0);

        // fragments: 16 warps 4(m) x 4(n), warp tile 32x32
        int wid = tid >> 5, lane = tid & 31;
        int wm  = (wid & 3) * 32;
        int wn  = (wid >> 2) * 32;
        int aRow = wm + (lane & 7) + ((lane & 8) ? 8 : 0);
        int aColF = (lane & 16) ? 4 : 0;
        unsigned aB = su32(Asm + aRow * 36 + aColF);
        // B pair-load addressing: lanes 16-31 target the second n-frag (+8 rows)
        int bRow = wn + (lane & 7) + ((lane & 16) ? 8 : 0);
        int bColF = (lane & 8) ? 4 : 0;
        unsigned bB = su32(Bsm + bRow * 36 + bColF);

        float acc[2][4][4];
#pragma unroll
        for (int i = 0; i < 2; i++)
#pragma unroll
            for (int j = 0; j < 4; j++)
#pragma unroll
                for (int v = 0; v < 4; v++) acc[i][j][v] = 0.f;

        __syncthreads();

#pragma unroll 1
        for (int kt = 0; kt < 8; kt++) {
            if (kt < 7) {                    // prefetch next k-slab
                int kq = (kt + 1) * 8;
#pragma unroll
                for (int j = 0; j < 2; j++) {
                    rg[j] = x4[aOff + kq + j];
                    rb[j] = x4[bOff + kq + j];
                    rw[j] = W4[wOff + kq + j];
                }
            }
            int buf = kt & 1;
            unsigned aS = aB + buf * TSTG * 4;
            unsigned bS = bB + buf * TSTG * 4;
#pragma unroll
            for (int ks = 0; ks < 4; ks++) {
                int k = ks * 8;
                unsigned af[2][4], bf[4][2];
#pragma unroll
                for (int mf = 0; mf < 2; mf++)
                    asm volatile("ldmatrix.sync.aligned.m8n8.x4.shared.b16 {%0,%1,%2,%3}, [%4];"
                        : "=r"(af[mf][0]), "=r"(af[mf][1]), "=r"(af[mf][2]), "=r"(af[mf][3])
                        : "r"(aS + (unsigned)((mf * 576 + k) * 4)));
#pragma unroll
                for (int np = 0; np < 2; np++)   // one x4 = two n-frags
                    asm volatile("ldmatrix.sync.aligned.m8n8.x4.shared.b16 {%0,%1,%2,%3}, [%4];"
                        : "=r"(bf[np*2][0]), "=r"(bf[np*2][1]),
                          "=r"(bf[np*2+1][0]), "=r"(bf[np*2+1][1])
                        : "r"(bS + (unsigned)((np * 576 + k) * 4)));
#pragma unroll
                for (int mf = 0; mf < 2; mf++)
#pragma unroll
                    for (int nf = 0; nf < 4; nf++)
                        asm volatile(
                            "mma.sync.aligned.m16n8k8.row.col.f32.tf32.tf32.f32 "
                            "{%0,%1,%2,%3}, {%4,%5,%6,%7}, {%8,%9}, {%0,%1,%2,%3};"
                            : "+f"(acc[mf][nf][0]), "+f"(acc[mf][nf][1]),
                              "+f"(acc[mf][nf][2]), "+f"(acc[mf][nf][3])
                            : "r"(af[mf][0]), "r"(af[mf][1]), "r"(af[mf][2]), "r"(af[mf][3]),
                              "r"(bf[nf][0]), "r"(bf[nf][1]));
            }
            if (kt < 7) {
                STORE_TILE(1 - buf);
                __syncthreads();
            }
        }

        int er = m0 + wm + (lane >> 2);
        int ec = n0 + wn + (lane & 3) * 2;
#pragma unroll
        for (int mf = 0; mf < 2; mf++) {
#pragma unroll
            for (int nf = 0; nf < 4; nf++) {
                float2 v0, v1;
                v0.x = lrelu(acc[mf][nf][0]); v0.y = lrelu(acc[mf][nf][1]);
                v1.x = lrelu(acc[mf][nf][2]); v1.y = lrelu(acc[mf][nf][3]);
                *(float2*)&out[(er + mf * 16) * DD + ec + nf * 8]     = v0;
                *(float2*)&out[(er + mf * 16 + 8) * DD + ec + nf * 8] = v1;
            }
        }
    }

    // ---- reset barrier counters for next graph replay (last block does it) ----
    __syncthreads();
    if (tid == 0) {
        unsigned old = atomicAdd(&g_bar3, 1u);
        if (old == GRID - 1) {
            g_bar1 = 0; g_bar2 = 0; g_bar3 = 0;
            __threadfence();
        }
    }
}

// ---------------- launch ---------------------------------------------------------
extern "C" void kernel_launch(void* const* d_in, const int* in_sizes, int n_in,
                              void* d_out, int out_size) {
    const float* x   = (const float*)d_in[0];
    const float* W   = (const float*)d_in[1];
    const float* a   = (const float*)d_in[2];
    const int*   dep = (const int*)d_in[3];
    const int*   gov = (const int*)d_in[4];
    float* out = (float*)d_out;

    int smem = 4 * TSTG * 4;   // 73,728 B
    cudaFuncSetAttribute(k_fused, cudaFuncAttributeMaxDynamicSharedMemorySize, smem);

    k_fused<<<GRID, 512, smem>>>(x, W, a, dep, gov, out);
}